// round 3
// baseline (speedup 1.0000x reference)
#include <cuda_runtime.h>
#include <cstdint>
#include <cstddef>

#define T_STEPS 2048
#define HID     128
#define BATCH   256

typedef unsigned long long ull;

// folded FC: M[128][3] then c[3]
__device__ float g_fold[128 * 3 + 4];

// ---- packed f32x2 helpers (sm_100+ PTX) ----
__device__ __forceinline__ ull fma2(ull a, ull b, ull c) {
    ull d;
    asm("fma.rn.f32x2 %0, %1, %2, %3;" : "=l"(d) : "l"(a), "l"(b), "l"(c));
    return d;
}
__device__ __forceinline__ ull add2(ull a, ull b) {
    ull d;
    asm("add.rn.f32x2 %0, %1, %2;" : "=l"(d) : "l"(a), "l"(b));
    return d;
}
__device__ __forceinline__ void unpack2(ull u, float& x, float& y) {
    asm("mov.b64 {%0, %1}, %2;" : "=f"(x), "=f"(y) : "l"(u));
}

// accurate-enough tanh that does NOT depend on fast-math lowering:
// tanh(|x|) = (1 - e)/(1 + e), e = exp(-2|x|) via MUFU EX2 (~2 ulp)
__device__ __forceinline__ float fast_tanh(float x) {
    float ax = fabsf(x);
    float e  = __expf(-2.0f * ax);
    float r  = __fdividef(1.0f - e, 1.0f + e);
    return copysignf(r, x);
}

// ---- tiny kernel: fold the two FC layers into a 128->3 affine map ----
__global__ void fold_kernel(const float* __restrict__ W_fc1,
                            const float* __restrict__ b_fc1,
                            const float* __restrict__ W_fc2,
                            const float* __restrict__ b_fc2) {
    int h = threadIdx.x;  // 0..127
    float m0 = 0.f, m1 = 0.f, m2 = 0.f;
    #pragma unroll 8
    for (int f = 0; f < 64; f++) {
        float w = W_fc1[f * 128 + h];
        m0 = fmaf(w, W_fc2[0 * 64 + f], m0);
        m1 = fmaf(w, W_fc2[1 * 64 + f], m1);
        m2 = fmaf(w, W_fc2[2 * 64 + f], m2);
    }
    g_fold[h * 3 + 0] = m0;
    g_fold[h * 3 + 1] = m1;
    g_fold[h * 3 + 2] = m2;
    if (h < 3) {
        float c = b_fc2[h];
        for (int f = 0; f < 64; f++) c = fmaf(b_fc1[f], W_fc2[h * 64 + f], c);
        g_fold[384 + h] = c;
    }
}

// shared layout (floats):
//   x_sh  : 2*2048*3 = 12288
//   h_sh  : 2*128    = 256
//   ring  : 2*64*129 = 16512   (pitch 129 -> conflict-free FC reads/writes)
//   Msh   : 384
//   csh   : 4
#define SMEM_FLOATS (12288 + 256 + 16512 + 384 + 4)
#define SMEM_BYTES  (SMEM_FLOATS * 4)

__global__ __launch_bounds__(128, 1)
void rnn_kernel(const float* __restrict__ x,
                const float* __restrict__ hidden,
                const float* __restrict__ W_ih,
                const float* __restrict__ W_hh,
                const float* __restrict__ b_ih,
                const float* __restrict__ b_hh,
                float* __restrict__ out) {
    extern __shared__ float sm[];
    float* x_sh = sm;                    // [2][2048*3]
    float* h_sh = sm + 12288;            // [2][128]
    float* ring = sm + 12288 + 256;      // [2][64][129]
    float* Msh  = ring + 16512;          // [128][3]
    float* csh  = Msh + 384;             // [3]

    const int j  = threadIdx.x;          // hidden index this thread owns
    const int r0 = blockIdx.x * 2;       // first of 2 batch rows

    // stage x for both rows (rows are contiguous in gmem)
    const float* xg = x + (size_t)r0 * (T_STEPS * 3);
    for (int idx = j; idx < 2 * T_STEPS * 3; idx += 128) x_sh[idx] = xg[idx];

    // stage folded FC map
    for (int idx = j; idx < 384; idx += 128) Msh[idx] = g_fold[idx];
    if (j < 3) csh[j] = g_fold[384 + j];

    // initial hidden state
    h_sh[j]       = hidden[(size_t)r0 * HID + j];
    h_sh[128 + j] = hidden[(size_t)(r0 + 1) * HID + j];

    // W_hh row j resident in registers as 64 packed f32x2
    ull w[64];
    const ull* wrow = (const ull*)(W_hh + j * HID);
    #pragma unroll
    for (int i = 0; i < 64; i++) w[i] = wrow[i];

    const float wi0 = W_ih[j * 3 + 0];
    const float wi1 = W_ih[j * 3 + 1];
    const float wi2 = W_ih[j * 3 + 2];
    const float bc  = b_ih[j] + b_hh[j];

    __syncthreads();

    for (int t = 0; t < T_STEPS; t++) {
        // input projection (x has only 3 features)
        float xa0 = x_sh[t * 3 + 0], xa1 = x_sh[t * 3 + 1], xa2 = x_sh[t * 3 + 2];
        float xb0 = x_sh[6144 + t * 3 + 0], xb1 = x_sh[6144 + t * 3 + 1], xb2 = x_sh[6144 + t * 3 + 2];
        float s0 = fmaf(wi2, xa2, fmaf(wi1, xa1, fmaf(wi0, xa0, bc)));
        float s1 = fmaf(wi2, xb2, fmaf(wi1, xb1, fmaf(wi0, xb0, bc)));

        // h . W_hh[j] for both rows, packed f32x2, 4 chains each
        ull a0 = 0, a1 = 0, a2 = 0, a3 = 0;
        ull b0 = 0, b1 = 0, b2 = 0, b3 = 0;
        const ulonglong2* hA = (const ulonglong2*)(h_sh);
        const ulonglong2* hB = (const ulonglong2*)(h_sh + 128);
        #pragma unroll
        for (int i = 0; i < 32; i++) {
            ulonglong2 va = hA[i];
            ulonglong2 vb = hB[i];
            if (i & 1) {
                a2 = fma2(va.x, w[2 * i], a2);
                a3 = fma2(va.y, w[2 * i + 1], a3);
                b2 = fma2(vb.x, w[2 * i], b2);
                b3 = fma2(vb.y, w[2 * i + 1], b3);
            } else {
                a0 = fma2(va.x, w[2 * i], a0);
                a1 = fma2(va.y, w[2 * i + 1], a1);
                b0 = fma2(vb.x, w[2 * i], b0);
                b1 = fma2(vb.y, w[2 * i + 1], b1);
            }
        }
        ull ra = add2(add2(a0, a2), add2(a1, a3));
        ull rb = add2(add2(b0, b2), add2(b1, b3));
        float fa0, fa1, fb0, fb1;
        unpack2(ra, fa0, fa1);
        unpack2(rb, fb0, fb1);
        float h0n = fast_tanh(s0 + (fa0 + fa1));
        float h1n = fast_tanh(s1 + (fb0 + fb1));

        __syncthreads();  // all reads of h_sh done
        int tl = t & 63;
        h_sh[j]       = h0n;
        h_sh[128 + j] = h1n;
        ring[tl * 129 + j]            = h0n;
        ring[64 * 129 + tl * 129 + j] = h1n;
        __syncthreads();  // new h + ring visible

        // every 64 steps: fused (folded) FC for the 128 (row,t) pairs in the ring
        if (tl == 63) {
            int rr  = j >> 6;          // which row
            int ttl = j & 63;          // which timestep in ring
            const float* hr = ring + rr * (64 * 129) + ttl * 129;
            float o0 = csh[0], o1 = csh[1], o2 = csh[2];
            #pragma unroll 16
            for (int k = 0; k < 128; k++) {
                float hv = hr[k];
                o0 = fmaf(hv, Msh[3 * k + 0], o0);
                o1 = fmaf(hv, Msh[3 * k + 1], o1);
                o2 = fmaf(hv, Msh[3 * k + 2], o2);
            }
            int tg = t - 63 + ttl;
            size_t rg = (size_t)(r0 + rr);
            float* op = out + (rg * T_STEPS + tg) * 3;
            op[0] = o0; op[1] = o1; op[2] = o2;
        }
    }

    // final hidden state -> second output region [1,B,128]
    float* hT = out + (size_t)BATCH * T_STEPS * 3;
    hT[(size_t)r0 * HID + j]       = h_sh[j];
    hT[(size_t)(r0 + 1) * HID + j] = h_sh[128 + j];
}

extern "C" void kernel_launch(void* const* d_in, const int* in_sizes, int n_in,
                              void* d_out, int out_size) {
    const float* x      = (const float*)d_in[0];
    const float* hidden = (const float*)d_in[1];
    const float* W_ih   = (const float*)d_in[2];
    const float* W_hh   = (const float*)d_in[3];
    const float* b_ih   = (const float*)d_in[4];
    const float* b_hh   = (const float*)d_in[5];
    const float* W_fc1  = (const float*)d_in[6];
    const float* b_fc1  = (const float*)d_in[7];
    const float* W_fc2  = (const float*)d_in[8];
    const float* b_fc2  = (const float*)d_in[9];
    float* out = (float*)d_out;

    cudaFuncSetAttribute(rnn_kernel, cudaFuncAttributeMaxDynamicSharedMemorySize, SMEM_BYTES);

    fold_kernel<<<1, 128>>>(W_fc1, b_fc1, W_fc2, b_fc2);
    rnn_kernel<<<BATCH / 2, 128, SMEM_BYTES>>>(x, hidden, W_ih, W_hh, b_ih, b_hh, out);
}